// round 14
// baseline (speedup 1.0000x reference)
#include <cuda_runtime.h>
#include <cuda_fp16.h>
#include <cstdint>

#define BSZ   128
#define NNODE 4000
#define DF    128
#define NB    10
#define SEQ   400
#define C1    32
#define C2    32
#define MTILE 128
#define MTOT  (BSZ*SEQ)          // 51200
#define NCTA  (MTOT/MTILE)       // 400
#define NSTAGE 20                // NB * 2 half-K stages, ring-3 buffers

// ---- shared memory byte layout (dynamic) ----------------------------------
#define SMB_IDX   0                         // 1280 u16 recep values = 2560 B
#define SMB_A     2560                      // 3 x 32 KB fp32 half-K stages
#define A_STAGE   (MTILE*64*4)              // 32768
#define SMB_B     (SMB_A + 3*A_STAGE)       // 100864
#define B_STAGE   4608                      // 32 pair-rows x 144 B ([fr][nt] u32)
#define SMB_TOTAL (SMB_B + 3*B_STAGE)       // 114688 -> 2 CTAs/SM

__device__ uint32_t g_w1h[NB*64*36];  // f16 pairs: [k][pair(d/2)][fr*4+nt]
__device__ float    g_partial[MTOT];
__device__ int      g_cnt[BSZ];       // zero-init; self-resetting per call

__device__ __forceinline__ uint32_t smem_u32(const void* p) {
    uint32_t a;
    asm("{ .reg .u64 t; cvta.to.shared.u64 t, %1; cvt.u32.u64 %0, t; }" : "=r"(a) : "l"(p));
    return a;
}
__device__ __forceinline__ void cp16(uint32_t dst, const void* src) {
    asm volatile("cp.async.cg.shared.global [%0], [%1], 16;" :: "r"(dst), "l"(src));
}
#define CP_COMMIT() asm volatile("cp.async.commit_group;" ::: "memory")
#define CP_WAIT(N)  asm volatile("cp.async.wait_group %0;" :: "n"(N) : "memory")

__device__ __forceinline__ uint32_t packh2(float2 v) {
    uint32_t r;
    asm("cvt.rn.f16x2.f32 %0, %1, %2;" : "=r"(r) : "f"(v.y), "f"(v.x));
    return r;
}
__device__ __forceinline__ void mma16816(float* c, uint32_t a0, uint32_t a1,
                                         uint32_t a2, uint32_t a3,
                                         uint32_t b0, uint32_t b1) {
    asm volatile(
        "mma.sync.aligned.m16n8k16.row.col.f32.f16.f16.f32 "
        "{%0,%1,%2,%3}, {%4,%5,%6,%7}, {%8,%9}, {%0,%1,%2,%3};"
        : "+f"(c[0]), "+f"(c[1]), "+f"(c[2]), "+f"(c[3])
        : "r"(a0), "r"(a1), "r"(a2), "r"(a3), "r"(b0), "r"(b1));
}

// ---------------------------------------------------------------------------
// prep: conv1 weights -> f16 pairs [k][d/2][fr*4+nt] (36-u32 rows)
//       value for c1 = nt*8+fr lands at u32 slot fr*4+nt
// ---------------------------------------------------------------------------
__global__ void prep_kernel(const float* __restrict__ w1) {
    int i = blockIdx.x * blockDim.x + threadIdx.x;     // 40960
    if (i >= NB * DF * C1) return;
    int k   = i >> 12;
    int rem = i & 4095;
    int d   = rem >> 5;
    int c1  = rem & 31;
    float v = w1[c1 * (DF * NB) + d * NB + k];
    int slot = (c1 & 7) * 4 + (c1 >> 3);
    ((__half*)g_w1h)[((size_t)k * 2304 + (d >> 1) * 36 + slot) * 2 + (d & 1)] =
        __float2half_rn(v);
}

// ---------------------------------------------------------------------------
// fused: ring-3 single-barrier cp.async pipeline + f16 mma conv1 + relu
//        + conv2 + relu + FC partial + last-CTA-per-graph reduction
// ---------------------------------------------------------------------------
__global__ __launch_bounds__(256, 2) void conv_kernel(
    const int*   __restrict__ recep,
    const float* __restrict__ nf,
    const float* __restrict__ b1,
    const float* __restrict__ w2,
    const float* __restrict__ b2,
    const float* __restrict__ fcw,
    const float* __restrict__ fcb,
    float*       __restrict__ out)
{
    extern __shared__ char smem[];
    const uint32_t sbase = smem_u32(smem);
    uint16_t* sIdx16 = (uint16_t*)(smem + SMB_IDX);
    const int tid  = threadIdx.x;
    const int wid  = tid >> 5;
    const int lane = tid & 31;
    const int m0   = blockIdx.x * MTILE;
    const int fr   = lane >> 2;      // 0..7
    const int fc   = lane & 3;       // 0..3

    // u16 recep table: 128 rows x 10 neighbors
    for (int i = tid; i < MTILE * NB; i += 256) {
        int row = i / NB;
        int k   = i - row * NB;
        int m   = m0 + row;
        int b   = m / SEQ;
        int s   = m - b * SEQ;
        sIdx16[i] = (uint16_t)recep[b * NNODE + s * NB + k];
    }
    __syncthreads();

    // per-thread gather constants (slot = tid + j*256 pattern)
    const int rbase = tid >> 4;               // row for j=0; rows rbase + 16j
    const int q     = tid & 15;               // float4 index within row-half
    uint32_t rowbase8[8];
#pragma unroll
    for (int j = 0; j < 8; j++) {
        int m = m0 + rbase + j * 16;
        rowbase8[j] = (uint32_t)(m / SEQ) * (NNODE * DF * 4);
    }
    const uint32_t adst = sbase + SMB_A + (uint32_t)rbase * 256u +
                          (uint32_t)((q ^ ((rbase & 7) << 1)) * 16);
    const char* nfq = (const char*)nf + q * 16;

    // stage s: k = s>>1, half h = s&1 (64 K-cols), buffer bi = s%3
    auto prefetch = [&](int s, int bi) {
        const int k = s >> 1, h = s & 1;
        const char* src0 = nfq + h * 256;
        const int io = rbase * NB + k;
        const uint32_t d0 = adst + (uint32_t)(bi * A_STAGE);
#pragma unroll
        for (int j = 0; j < 8; j++) {
            uint32_t off = (uint32_t)sIdx16[io + j * 160] * 512u + rowbase8[j];
            cp16(d0 + (uint32_t)(j * 4096), src0 + off);
        }
        // B: dense 4608 B = 288 cp16 (needs 2 rounds at 256 threads!)
        {
            const uint32_t bbase = sbase + SMB_B + (uint32_t)(bi * B_STAGE);
            const char* bsrc = (const char*)g_w1h + (size_t)k * 9216 + h * 4608;
#pragma unroll
            for (int j = 0; j < 2; j++) {
                int slot = tid + j * 256;
                if (slot < 288)
                    cp16(bbase + (uint32_t)(slot * 16), bsrc + slot * 16);
            }
        }
        CP_COMMIT();
    };

    prefetch(0, 0);
    prefetch(1, 1);

    float acc[4][4];
#pragma unroll
    for (int nt = 0; nt < 4; nt++)
#pragma unroll
        for (int j = 0; j < 4; j++) acc[nt][j] = 0.f;

    const int row0 = wid * 16 + fr;
    const int sw   = fr << 1;
    const int oi   = (fc & 1) * 2;

    int bi = 0;                               // = s % 3
    for (int s = 0; s < NSTAGE; s++) {
        if (s < NSTAGE - 1) CP_WAIT(1); else CP_WAIT(0);
        __syncthreads();   // stage s visible; all warps past compute(s-1)

        const float*    aw = (const float*)(smem + SMB_A + bi * A_STAGE);
        const uint32_t* bw = (const uint32_t*)(smem + SMB_B + bi * B_STAGE);
#pragma unroll
        for (int t = 0; t < 4; t++) {
            const int q0 = (4 * t + (fc >> 1)) ^ sw;       // cols 16t+2fc
            const int q1 = (4 * t + 2 + (fc >> 1)) ^ sw;   // cols 16t+8+2fc
            float2 v00 = *(const float2*)(aw + row0 * 64       + q0 * 4 + oi);
            float2 v10 = *(const float2*)(aw + (row0 + 8) * 64 + q0 * 4 + oi);
            float2 v01 = *(const float2*)(aw + row0 * 64       + q1 * 4 + oi);
            float2 v11 = *(const float2*)(aw + (row0 + 8) * 64 + q1 * 4 + oi);
            uint32_t a0 = packh2(v00), a1 = packh2(v10);
            uint32_t a2 = packh2(v01), a3 = packh2(v11);
            // B: one LDS.128 per pair-row gives nt 0..3 for this fr
            uint4 bq0 = *(const uint4*)(bw + (8 * t + fc)     * 36 + fr * 4);
            uint4 bq1 = *(const uint4*)(bw + (8 * t + 4 + fc) * 36 + fr * 4);
            mma16816(acc[0], a0, a1, a2, a3, bq0.x, bq1.x);
            mma16816(acc[1], a0, a1, a2, a3, bq0.y, bq1.y);
            mma16816(acc[2], a0, a1, a2, a3, bq0.z, bq1.z);
            mma16816(acc[3], a0, a1, a2, a3, bq0.w, bq1.w);
        }
        // refill buffer (s+2)%3: its last readers (stage s-1) passed barrier(s)
        if (s + 2 < NSTAGE) {
            int bn = bi + 2; if (bn >= 3) bn -= 3;
            prefetch(s + 2, bn);
        }
        if (++bi == 3) bi = 0;
    }
    __syncthreads();   // all warps done with all buffers

    // y1 = relu(conv1 + b1) -> smem [128][33] (buf0); w2 -> buf1 region
    float* y1s = (float*)(smem + SMB_A);
    float* w2s = (float*)(smem + SMB_A + A_STAGE);
    const int rb = wid * 16;
#pragma unroll
    for (int nt = 0; nt < 4; nt++) {
        int col = nt * 8 + 2 * fc;
        float bc0 = __ldg(b1 + col), bc1 = __ldg(b1 + col + 1);
        y1s[(rb + fr)     * 33 + col]     = fmaxf(acc[nt][0] + bc0, 0.f);
        y1s[(rb + fr)     * 33 + col + 1] = fmaxf(acc[nt][1] + bc1, 0.f);
        y1s[(rb + fr + 8) * 33 + col]     = fmaxf(acc[nt][2] + bc0, 0.f);
        y1s[(rb + fr + 8) * 33 + col + 1] = fmaxf(acc[nt][3] + bc1, 0.f);
    }
    ((float4*)w2s)[tid] = ((const float4*)w2)[tid & 255];
    __syncthreads();

    // conv2 (fp32) + relu + FC partial: one thread per row
    if (tid < MTILE) {
        int m = m0 + tid;
        int b = m / SEQ;
        int s = m - b * SEQ;
        const float* yr = y1s + tid * 33;
        float p = 0.f;
#pragma unroll
        for (int c2 = 0; c2 < C2; c2++) {
            float v = __ldg(b2 + c2);
            const float* wv = w2s + c2 * 32;
#pragma unroll
            for (int qq = 0; qq < 32; qq += 4) {
                v = fmaf(wv[qq],     yr[qq],     v);
                v = fmaf(wv[qq + 1], yr[qq + 1], v);
                v = fmaf(wv[qq + 2], yr[qq + 2], v);
                v = fmaf(wv[qq + 3], yr[qq + 3], v);
            }
            v = fmaxf(v, 0.f);
            p = fmaf(v, __ldg(fcw + c2 * SEQ + s), p);
        }
        g_partial[m] = p;
        __threadfence();
    }
    __syncthreads();

    // --- deterministic final reduction: last CTA to finish a graph sums it
    int*   sfin = (int*)(smem + SMB_B + B_STAGE);      // reuse B regions
    float* sred = (float*)(smem + SMB_B);
    if (tid == 0) {
        int bA = m0 / SEQ;
        int bB = (m0 + MTILE - 1) / SEQ;
        sfin[0] = -1; sfin[1] = -1;
#pragma unroll 2
        for (int j = 0; j < 2; j++) {
            int b = bA + j;
            if (b > bB) break;
            int lo = max(b * SEQ, m0);
            int hi = min((b + 1) * SEQ, m0 + MTILE);
            int my = hi - lo;
            int old = atomicAdd(&g_cnt[b], my);
            if (old + my == SEQ) sfin[j] = b;
        }
    }
    __syncthreads();

#pragma unroll 2
    for (int j = 0; j < 2; j++) {
        int b = sfin[j];
        if (b < 0) continue;
        __threadfence();                     // acquire other CTAs' partials
        float s = 0.f;
        for (int i = tid; i < SEQ; i += 256) s += g_partial[b * SEQ + i];
        sred[tid] = s;
        __syncthreads();
        for (int st = 128; st > 0; st >>= 1) {
            if (tid < st) sred[tid] += sred[tid + st];
            __syncthreads();
        }
        if (tid == 0) {
            out[b] = sred[0] + __ldg(fcb);
            g_cnt[b] = 0;                    // reset for graph replay
        }
        __syncthreads();
    }
}

// ---------------------------------------------------------------------------
extern "C" void kernel_launch(void* const* d_in, const int* in_sizes, int n_in,
                              void* d_out, int out_size) {
    const int*   recep = (const int*)  d_in[0];
    const float* nf    = (const float*)d_in[1];
    const float* w1    = (const float*)d_in[2];
    const float* b1    = (const float*)d_in[3];
    const float* w2    = (const float*)d_in[4];
    const float* b2    = (const float*)d_in[5];
    const float* fcw   = (const float*)d_in[6];
    const float* fcb   = (const float*)d_in[7];
    float* out = (float*)d_out;

    cudaFuncSetAttribute(conv_kernel, cudaFuncAttributeMaxDynamicSharedMemorySize, SMB_TOTAL);
    prep_kernel<<<(NB*DF*C1 + 255) / 256, 256>>>(w1);
    conv_kernel<<<NCTA, 256, SMB_TOTAL>>>(recep, nf, b1, w2, b2, fcw, fcb, out);
}

// round 15
// speedup vs baseline: 1.1744x; 1.1744x over previous
#include <cuda_runtime.h>
#include <cuda_fp16.h>
#include <cstdint>

#define BSZ   128
#define NNODE 4000
#define DF    128
#define NB    10
#define SEQ   400
#define C1    32
#define C2    32
#define MTILE 128
#define MTOT  (BSZ*SEQ)          // 51200
#define NCTA  (MTOT/MTILE)       // 400
#define NSTAGE 20                // NB * 2 half-K stages

// ---- shared memory byte layout (dynamic) ----------------------------------
#define SMB_IDX   0                         // 1280 u16 recep values = 2560 B
#define SMB_A     2560                      // 2 x 32 KB fp32 half-K stages
#define A_STAGE   (MTILE*64*4)              // 32768
#define SMB_B     (SMB_A + 2*A_STAGE)       // 68096
#define B_STAGE   4096                      // dense 32 pair-rows x 128 B, swizzled
#define SMB_TOTAL (SMB_B + 2*B_STAGE)       // 76288 -> 3 CTAs/SM

__device__ uint32_t g_w1h[NB*64*32];  // dense f16 pairs: [k][pair(d/2)][c1]
__device__ float    g_partial[MTOT];
__device__ int      g_cnt[BSZ];       // zero-init; self-resetting per call

__device__ __forceinline__ uint32_t smem_u32(const void* p) {
    uint32_t a;
    asm("{ .reg .u64 t; cvta.to.shared.u64 t, %1; cvt.u32.u64 %0, t; }" : "=r"(a) : "l"(p));
    return a;
}
__device__ __forceinline__ void cp16(uint32_t dst, const void* src) {
    asm volatile("cp.async.cg.shared.global [%0], [%1], 16;" :: "r"(dst), "l"(src));
}
#define CP_COMMIT() asm volatile("cp.async.commit_group;" ::: "memory")
#define CP_WAIT(N)  asm volatile("cp.async.wait_group %0;" :: "n"(N) : "memory")

__device__ __forceinline__ uint32_t packh2(float2 v) {
    uint32_t r;
    asm("cvt.rn.f16x2.f32 %0, %1, %2;" : "=r"(r) : "f"(v.y), "f"(v.x));
    return r;
}
__device__ __forceinline__ void mma16816(float* c, uint32_t a0, uint32_t a1,
                                         uint32_t a2, uint32_t a3,
                                         uint32_t b0, uint32_t b1) {
    asm volatile(
        "mma.sync.aligned.m16n8k16.row.col.f32.f16.f16.f32 "
        "{%0,%1,%2,%3}, {%4,%5,%6,%7}, {%8,%9}, {%0,%1,%2,%3};"
        : "+f"(c[0]), "+f"(c[1]), "+f"(c[2]), "+f"(c[3])
        : "r"(a0), "r"(a1), "r"(a2), "r"(a3), "r"(b0), "r"(b1));
}

// ---------------------------------------------------------------------------
// prep: conv1 weights -> dense f16 pair-interleaved [k][d/2][c1]
// One block per c1: reads w1[c1][*][*] = 1280 CONTIGUOUS floats (coalesced),
// writes scattered 2B halves (latency-insensitive stores).
// ---------------------------------------------------------------------------
__global__ void prep_kernel(const float* __restrict__ w1) {
    const int c1 = blockIdx.x;                     // 0..31
    const float* src = w1 + c1 * (DF * NB);        // [d][k] row, 1280 floats
    __half* dst = (__half*)g_w1h;
#pragma unroll
    for (int j = threadIdx.x; j < DF * NB; j += 256) {
        int d = j / NB;
        int k = j - d * NB;
        dst[((size_t)k * 2048 + (d >> 1) * 32 + c1) * 2 + (d & 1)] =
            __float2half_rn(src[j]);
    }
}

// ---------------------------------------------------------------------------
// fused: R6-shape cp.async pipeline + f16 mma conv1 + relu + conv2 + relu
//        + FC partial + deterministic last-CTA-per-graph reduction
// ---------------------------------------------------------------------------
__global__ __launch_bounds__(256, 3) void conv_kernel(
    const int*   __restrict__ recep,
    const float* __restrict__ nf,
    const float* __restrict__ b1,
    const float* __restrict__ w2,
    const float* __restrict__ b2,
    const float* __restrict__ fcw,
    const float* __restrict__ fcb,
    float*       __restrict__ out)
{
    extern __shared__ char smem[];
    const uint32_t sbase = smem_u32(smem);
    uint16_t* sIdx16 = (uint16_t*)(smem + SMB_IDX);
    const int tid  = threadIdx.x;
    const int wid  = tid >> 5;
    const int lane = tid & 31;
    const int m0   = blockIdx.x * MTILE;
    const int fr   = lane >> 2;      // 0..7
    const int fc   = lane & 3;       // 0..3

    // u16 recep table: 128 rows x 10 neighbors
    for (int i = tid; i < MTILE * NB; i += 256) {
        int row = i / NB;
        int k   = i - row * NB;
        int m   = m0 + row;
        int b   = m / SEQ;
        int s   = m - b * SEQ;
        sIdx16[i] = (uint16_t)recep[b * NNODE + s * NB + k];
    }
    __syncthreads();

    // per-thread gather constants (slot = tid + j*256 pattern)
    const int rbase = tid >> 4;               // row for j=0; rows rbase + 16j
    const int q     = tid & 15;               // float4 index within row-half
    uint32_t rowbase8[8];                     // graph base byte offsets
#pragma unroll
    for (int j = 0; j < 8; j++) {
        int m = m0 + rbase + j * 16;
        rowbase8[j] = (uint32_t)(m / SEQ) * (NNODE * DF * 4);
    }
    const uint32_t adst = sbase + SMB_A + (uint32_t)rbase * 256u +
                          (uint32_t)((q ^ ((rbase & 7) << 1)) * 16);
    const char* nfq = (const char*)nf + q * 16;

    // stage s: k = s>>1, half h = s&1 (64 K-cols), buffer bi = s&1
    auto prefetch = [&](int s) {
        const int k = s >> 1, h = s & 1, bi = s & 1;
        const char* src0 = nfq + h * 256;
        const int io = rbase * NB + k;
        const uint32_t d0 = adst + (uint32_t)(bi * A_STAGE);
#pragma unroll
        for (int j = 0; j < 8; j++) {
            uint32_t off = (uint32_t)sIdx16[io + j * 160] * 512u + rowbase8[j];
            cp16(d0 + (uint32_t)(j * 4096), src0 + off);
        }
        // B: dense swizzled 4 KB (one cp16 per thread)
        {
            int row = tid >> 3, c4 = tid & 7;
            int c4p = c4 ^ ((row & 3) << 1);
            cp16(sbase + SMB_B + (uint32_t)(bi * B_STAGE) +
                     (uint32_t)(row * 128 + c4p * 16),
                 (const char*)g_w1h + (size_t)k * 8192 + h * 4096 + tid * 16);
        }
        CP_COMMIT();
    };

    prefetch(0);
    prefetch(1);

    float acc[4][4];
#pragma unroll
    for (int nt = 0; nt < 4; nt++)
#pragma unroll
        for (int j = 0; j < 4; j++) acc[nt][j] = 0.f;

    const int row0 = wid * 16 + fr;
    const int sw   = fr << 1;
    const int oi   = (fc & 1) * 2;
    const int bxor = fc << 3;                 // B column swizzle for this lane

    for (int s = 0; s < NSTAGE; s++) {
        const int bi = s & 1;
        if (s < NSTAGE - 1) CP_WAIT(1); else CP_WAIT(0);
        __syncthreads();

        const float*    aw = (const float*)(smem + SMB_A + bi * A_STAGE);
        const uint32_t* bw = (const uint32_t*)(smem + SMB_B + bi * B_STAGE);
#pragma unroll
        for (int t = 0; t < 4; t++) {
            const int q0 = (4 * t + (fc >> 1)) ^ sw;       // cols 16t+2fc
            const int q1 = (4 * t + 2 + (fc >> 1)) ^ sw;   // cols 16t+8+2fc
            float2 v00 = *(const float2*)(aw + row0 * 64       + q0 * 4 + oi);
            float2 v10 = *(const float2*)(aw + (row0 + 8) * 64 + q0 * 4 + oi);
            float2 v01 = *(const float2*)(aw + row0 * 64       + q1 * 4 + oi);
            float2 v11 = *(const float2*)(aw + (row0 + 8) * 64 + q1 * 4 + oi);
            uint32_t a0 = packh2(v00), a1 = packh2(v10);
            uint32_t a2 = packh2(v01), a3 = packh2(v11);
            const int p0 = (8 * t + fc) * 32;          // pair-row k = 16t+2fc
            const int p1 = (8 * t + 4 + fc) * 32;      // pair-row k = 16t+8+2fc
#pragma unroll
            for (int nt = 0; nt < 4; nt++) {
                const int col = (nt * 8 + fr) ^ bxor;
                uint32_t b0  = bw[p0 + col];
                uint32_t b1v = bw[p1 + col];
                mma16816(acc[nt], a0, a1, a2, a3, b0, b1v);
            }
        }
        __syncthreads();                            // done reading stage bi
        if (s + 2 < NSTAGE) prefetch(s + 2);        // refill freed buffer
    }

    // y1 = relu(conv1 + b1) -> smem [128][33]; w2 -> stage-1 A region
    float* y1s = (float*)(smem + SMB_A);
    float* w2s = (float*)(smem + SMB_A + A_STAGE);
    const int rb = wid * 16;
#pragma unroll
    for (int nt = 0; nt < 4; nt++) {
        int col = nt * 8 + 2 * fc;
        float bc0 = __ldg(b1 + col), bc1 = __ldg(b1 + col + 1);
        y1s[(rb + fr)     * 33 + col]     = fmaxf(acc[nt][0] + bc0, 0.f);
        y1s[(rb + fr)     * 33 + col + 1] = fmaxf(acc[nt][1] + bc1, 0.f);
        y1s[(rb + fr + 8) * 33 + col]     = fmaxf(acc[nt][2] + bc0, 0.f);
        y1s[(rb + fr + 8) * 33 + col + 1] = fmaxf(acc[nt][3] + bc1, 0.f);
    }
    ((float4*)w2s)[tid] = ((const float4*)w2)[tid & 255];
    __syncthreads();

    // conv2 (fp32) + relu + FC partial: one thread per row
    if (tid < MTILE) {
        int m = m0 + tid;
        int b = m / SEQ;
        int s = m - b * SEQ;
        const float* yr = y1s + tid * 33;
        float p = 0.f;
#pragma unroll
        for (int c2 = 0; c2 < C2; c2++) {
            float v = __ldg(b2 + c2);
            const float* wv = w2s + c2 * 32;
#pragma unroll
            for (int qq = 0; qq < 32; qq += 4) {
                v = fmaf(wv[qq],     yr[qq],     v);
                v = fmaf(wv[qq + 1], yr[qq + 1], v);
                v = fmaf(wv[qq + 2], yr[qq + 2], v);
                v = fmaf(wv[qq + 3], yr[qq + 3], v);
            }
            v = fmaxf(v, 0.f);
            p = fmaf(v, __ldg(fcw + c2 * SEQ + s), p);
        }
        g_partial[m] = p;
        __threadfence();
    }
    __syncthreads();

    // --- deterministic final reduction: last CTA to finish a graph sums it
    int*   sfin = (int*)(smem + SMB_B + B_STAGE);      // reuse B stage-1 region
    float* sred = (float*)(smem + SMB_B);              // reuse B stage-0 region
    if (tid == 0) {
        int bA = m0 / SEQ;
        int bB = (m0 + MTILE - 1) / SEQ;
        sfin[0] = -1; sfin[1] = -1;
#pragma unroll 2
        for (int j = 0; j < 2; j++) {
            int b = bA + j;
            if (b > bB) break;
            int lo = max(b * SEQ, m0);
            int hi = min((b + 1) * SEQ, m0 + MTILE);
            int my = hi - lo;
            int old = atomicAdd(&g_cnt[b], my);
            if (old + my == SEQ) sfin[j] = b;
        }
    }
    __syncthreads();

#pragma unroll 2
    for (int j = 0; j < 2; j++) {
        int b = sfin[j];
        if (b < 0) continue;
        __threadfence();                     // acquire other CTAs' partials
        float s = 0.f;
        for (int i = tid; i < SEQ; i += 256) s += g_partial[b * SEQ + i];
        sred[tid] = s;
        __syncthreads();
        for (int st = 128; st > 0; st >>= 1) {
            if (tid < st) sred[tid] += sred[tid + st];
            __syncthreads();
        }
        if (tid == 0) {
            out[b] = sred[0] + __ldg(fcb);
            g_cnt[b] = 0;                    // reset for graph replay
        }
        __syncthreads();
    }
}

// ---------------------------------------------------------------------------
extern "C" void kernel_launch(void* const* d_in, const int* in_sizes, int n_in,
                              void* d_out, int out_size) {
    const int*   recep = (const int*)  d_in[0];
    const float* nf    = (const float*)d_in[1];
    const float* w1    = (const float*)d_in[2];
    const float* b1    = (const float*)d_in[3];
    const float* w2    = (const float*)d_in[4];
    const float* b2    = (const float*)d_in[5];
    const float* fcw   = (const float*)d_in[6];
    const float* fcb   = (const float*)d_in[7];
    float* out = (float*)d_out;

    cudaFuncSetAttribute(conv_kernel, cudaFuncAttributeMaxDynamicSharedMemorySize, SMB_TOTAL);
    prep_kernel<<<C1, 256>>>(w1);
    conv_kernel<<<NCTA, 256, SMB_TOTAL>>>(recep, nf, b1, w2, b2, fcw, fcb, out);
}

// round 16
// speedup vs baseline: 1.2367x; 1.0531x over previous
#include <cuda_runtime.h>
#include <cuda_fp16.h>
#include <cstdint>

#define BSZ   128
#define NNODE 4000
#define DF    128
#define NB    10
#define SEQ   400
#define C1    32
#define C2    32
#define MTILE 128
#define MTOT  (BSZ*SEQ)          // 51200
#define NCTA  (MTOT/MTILE)       // 400
#define NSTAGE 20                // NB * 2 half-K stages

// ---- shared memory byte layout (dynamic) ----------------------------------
#define SMB_IDX   0                         // 1280 u16 recep values = 2560 B
#define SMB_A     2560                      // 2 x 32 KB fp32 half-K stages
#define A_STAGE   (MTILE*64*4)              // 32768
#define SMB_B     (SMB_A + 2*A_STAGE)       // 68096
#define B_STAGE   4096                      // dense 32 pair-rows x 128 B, block-rotated
#define SMB_TOTAL (SMB_B + 2*B_STAGE)       // 76288 -> 3 CTAs/SM

__device__ uint32_t g_w1h[NB*64*32];  // f16 pairs: [k][h][p][rot(blk)*4+nt]
__device__ float    g_partial[MTOT];
__device__ int      g_cnt[BSZ];       // zero-init; self-resetting per call

__device__ __forceinline__ uint32_t smem_u32(const void* p) {
    uint32_t a;
    asm("{ .reg .u64 t; cvta.to.shared.u64 t, %1; cvt.u32.u64 %0, t; }" : "=r"(a) : "l"(p));
    return a;
}
__device__ __forceinline__ void cp16(uint32_t dst, const void* src) {
    asm volatile("cp.async.cg.shared.global [%0], [%1], 16;" :: "r"(dst), "l"(src));
}
#define CP_COMMIT() asm volatile("cp.async.commit_group;" ::: "memory")
#define CP_WAIT(N)  asm volatile("cp.async.wait_group %0;" :: "n"(N) : "memory")

__device__ __forceinline__ uint32_t packh2(float2 v) {
    uint32_t r;
    asm("cvt.rn.f16x2.f32 %0, %1, %2;" : "=r"(r) : "f"(v.y), "f"(v.x));
    return r;
}
__device__ __forceinline__ void mma16816(float* c, uint32_t a0, uint32_t a1,
                                         uint32_t a2, uint32_t a3,
                                         uint32_t b0, uint32_t b1) {
    asm volatile(
        "mma.sync.aligned.m16n8k16.row.col.f32.f16.f16.f32 "
        "{%0,%1,%2,%3}, {%4,%5,%6,%7}, {%8,%9}, {%0,%1,%2,%3};"
        : "+f"(c[0]), "+f"(c[1]), "+f"(c[2]), "+f"(c[3])
        : "r"(a0), "r"(a1), "r"(a2), "r"(a3), "r"(b0), "r"(b1));
}

// ---------------------------------------------------------------------------
// prep: conv1 weights -> f16 pairs, [k][h][p]{ blockpos = (blk + 2*(p&3))&7 }
//       element (pair-row p, col c1): blk = c1&7, nt = c1>>3
//       u32 slot = p*32 + ((c1&7) + 2*(p&3) & 7)*4 + (c1>>3)
// ---------------------------------------------------------------------------
__global__ void prep_kernel(const float* __restrict__ w1) {
    int i = blockIdx.x * blockDim.x + threadIdx.x;     // 40960
    if (i >= NB * DF * C1) return;
    int k   = i >> 12;
    int rem = i & 4095;
    int d   = rem >> 5;
    int c1  = rem & 31;
    float v = w1[c1 * (DF * NB) + d * NB + k];
    int pair = d >> 1;
    int h    = pair >> 5;
    int p    = pair & 31;
    int perm = ((((c1 & 7) + 2 * (p & 3)) & 7) << 2) + (c1 >> 3);
    ((__half*)g_w1h)[((size_t)k * 2048 + h * 1024 + p * 32 + perm) * 2 + (d & 1)] =
        __float2half_rn(v);
}

// ---------------------------------------------------------------------------
// fused: R12 cp.async pipeline + f16 mma conv1 (LDS.128 B-fragments) + relu
//        + conv2 + relu + FC partial + last-CTA-per-graph reduction
// ---------------------------------------------------------------------------
__global__ __launch_bounds__(256, 3) void conv_kernel(
    const int*   __restrict__ recep,
    const float* __restrict__ nf,
    const float* __restrict__ b1,
    const float* __restrict__ w2,
    const float* __restrict__ b2,
    const float* __restrict__ fcw,
    const float* __restrict__ fcb,
    float*       __restrict__ out)
{
    extern __shared__ char smem[];
    const uint32_t sbase = smem_u32(smem);
    uint16_t* sIdx16 = (uint16_t*)(smem + SMB_IDX);
    const int tid  = threadIdx.x;
    const int wid  = tid >> 5;
    const int lane = tid & 31;
    const int m0   = blockIdx.x * MTILE;
    const int fr   = lane >> 2;      // 0..7
    const int fc   = lane & 3;       // 0..3

    // u16 recep table: 128 rows x 10 neighbors
    for (int i = tid; i < MTILE * NB; i += 256) {
        int row = i / NB;
        int k   = i - row * NB;
        int m   = m0 + row;
        int b   = m / SEQ;
        int s   = m - b * SEQ;
        sIdx16[i] = (uint16_t)recep[b * NNODE + s * NB + k];
    }
    __syncthreads();

    // per-thread gather constants (slot = tid + j*256 pattern)
    const int rbase = tid >> 4;               // row for j=0; rows rbase + 16j
    const int q     = tid & 15;               // float4 index within row-half
    uint32_t rowbase8[8];                     // graph base byte offsets
#pragma unroll
    for (int j = 0; j < 8; j++) {
        int m = m0 + rbase + j * 16;
        rowbase8[j] = (uint32_t)(m / SEQ) * (NNODE * DF * 4);
    }
    const uint32_t adst = sbase + SMB_A + (uint32_t)rbase * 256u +
                          (uint32_t)((q ^ ((rbase & 7) << 1)) * 16);
    const char* nfq = (const char*)nf + q * 16;

    // stage s: k = s>>1, half h = s&1 (64 K-cols), buffer bi = s&1
    auto prefetch = [&](int s) {
        const int k = s >> 1, h = s & 1, bi = s & 1;
        const char* src0 = nfq + h * 256;
        const int io = rbase * NB + k;
        const uint32_t d0 = adst + (uint32_t)(bi * A_STAGE);
#pragma unroll
        for (int j = 0; j < 8; j++) {
            uint32_t off = (uint32_t)sIdx16[io + j * 160] * 512u + rowbase8[j];
            cp16(d0 + (uint32_t)(j * 4096), src0 + off);
        }
        // B: dense 4 KB, permutation pre-baked in table -> straight copy
        cp16(sbase + SMB_B + (uint32_t)(bi * B_STAGE) + (uint32_t)(tid * 16),
             (const char*)g_w1h + (size_t)k * 8192 + h * 4096 + tid * 16);
        CP_COMMIT();
    };

    prefetch(0);
    prefetch(1);

    float acc[4][4];
#pragma unroll
    for (int nt = 0; nt < 4; nt++)
#pragma unroll
        for (int j = 0; j < 4; j++) acc[nt][j] = 0.f;

    const int row0  = wid * 16 + fr;
    const int sw    = fr << 1;
    const int oi    = (fc & 1) * 2;
    const int bperm = (((fr + 2 * fc) & 7) << 2);   // rotated block for (fr,fc)

    for (int s = 0; s < NSTAGE; s++) {
        const int bi = s & 1;
        if (s < NSTAGE - 1) CP_WAIT(1); else CP_WAIT(0);
        __syncthreads();

        const float*    aw = (const float*)(smem + SMB_A + bi * A_STAGE);
        const uint32_t* bw = (const uint32_t*)(smem + SMB_B + bi * B_STAGE);
#pragma unroll
        for (int t = 0; t < 4; t++) {
            const int q0 = (4 * t + (fc >> 1)) ^ sw;       // cols 16t+2fc
            const int q1 = (4 * t + 2 + (fc >> 1)) ^ sw;   // cols 16t+8+2fc
            float2 v00 = *(const float2*)(aw + row0 * 64       + q0 * 4 + oi);
            float2 v10 = *(const float2*)(aw + (row0 + 8) * 64 + q0 * 4 + oi);
            float2 v01 = *(const float2*)(aw + row0 * 64       + q1 * 4 + oi);
            float2 v11 = *(const float2*)(aw + (row0 + 8) * 64 + q1 * 4 + oi);
            uint32_t a0 = packh2(v00), a1 = packh2(v10);
            uint32_t a2 = packh2(v01), a3 = packh2(v11);
            // B: pair-rows 8t+fc and 8t+4+fc; one LDS.128 each, nt in components
            const uint32_t* bp = bw + (8 * t + fc) * 32 + bperm;
            uint4 bq0 = *(const uint4*)(bp);
            uint4 bq1 = *(const uint4*)(bp + 128);
            mma16816(acc[0], a0, a1, a2, a3, bq0.x, bq1.x);
            mma16816(acc[1], a0, a1, a2, a3, bq0.y, bq1.y);
            mma16816(acc[2], a0, a1, a2, a3, bq0.z, bq1.z);
            mma16816(acc[3], a0, a1, a2, a3, bq0.w, bq1.w);
        }
        __syncthreads();                            // done reading stage bi
        if (s + 2 < NSTAGE) prefetch(s + 2);        // refill freed buffer
    }

    // y1 = relu(conv1 + b1) -> smem [128][33]; w2 -> stage-1 A region
    float* y1s = (float*)(smem + SMB_A);
    float* w2s = (float*)(smem + SMB_A + A_STAGE);
    const int rb = wid * 16;
#pragma unroll
    for (int nt = 0; nt < 4; nt++) {
        int col = nt * 8 + 2 * fc;
        float bc0 = __ldg(b1 + col), bc1 = __ldg(b1 + col + 1);
        y1s[(rb + fr)     * 33 + col]     = fmaxf(acc[nt][0] + bc0, 0.f);
        y1s[(rb + fr)     * 33 + col + 1] = fmaxf(acc[nt][1] + bc1, 0.f);
        y1s[(rb + fr + 8) * 33 + col]     = fmaxf(acc[nt][2] + bc0, 0.f);
        y1s[(rb + fr + 8) * 33 + col + 1] = fmaxf(acc[nt][3] + bc1, 0.f);
    }
    ((float4*)w2s)[tid] = ((const float4*)w2)[tid & 255];
    __syncthreads();

    // conv2 (fp32) + relu + FC partial: one thread per row
    if (tid < MTILE) {
        int m = m0 + tid;
        int b = m / SEQ;
        int s = m - b * SEQ;
        const float* yr = y1s + tid * 33;
        float p = 0.f;
#pragma unroll
        for (int c2 = 0; c2 < C2; c2++) {
            float v = __ldg(b2 + c2);
            const float* wv = w2s + c2 * 32;
#pragma unroll
            for (int qq = 0; qq < 32; qq += 4) {
                v = fmaf(wv[qq],     yr[qq],     v);
                v = fmaf(wv[qq + 1], yr[qq + 1], v);
                v = fmaf(wv[qq + 2], yr[qq + 2], v);
                v = fmaf(wv[qq + 3], yr[qq + 3], v);
            }
            v = fmaxf(v, 0.f);
            p = fmaf(v, __ldg(fcw + c2 * SEQ + s), p);
        }
        g_partial[m] = p;
        __threadfence();
    }
    __syncthreads();

    // --- deterministic final reduction: last CTA to finish a graph sums it
    int*   sfin = (int*)(smem + SMB_B + B_STAGE);      // reuse B stage-1 region
    float* sred = (float*)(smem + SMB_B);              // reuse B stage-0 region
    if (tid == 0) {
        int bA = m0 / SEQ;
        int bB = (m0 + MTILE - 1) / SEQ;
        sfin[0] = -1; sfin[1] = -1;
#pragma unroll 2
        for (int j = 0; j < 2; j++) {
            int b = bA + j;
            if (b > bB) break;
            int lo = max(b * SEQ, m0);
            int hi = min((b + 1) * SEQ, m0 + MTILE);
            int my = hi - lo;
            int old = atomicAdd(&g_cnt[b], my);
            if (old + my == SEQ) sfin[j] = b;
        }
    }
    __syncthreads();

#pragma unroll 2
    for (int j = 0; j < 2; j++) {
        int b = sfin[j];
        if (b < 0) continue;
        __threadfence();                     // acquire other CTAs' partials
        float s = 0.f;
        for (int i = tid; i < SEQ; i += 256) s += g_partial[b * SEQ + i];
        sred[tid] = s;
        __syncthreads();
        for (int st = 128; st > 0; st >>= 1) {
            if (tid < st) sred[tid] += sred[tid + st];
            __syncthreads();
        }
        if (tid == 0) {
            out[b] = sred[0] + __ldg(fcb);
            g_cnt[b] = 0;                    // reset for graph replay
        }
        __syncthreads();
    }
}

// ---------------------------------------------------------------------------
extern "C" void kernel_launch(void* const* d_in, const int* in_sizes, int n_in,
                              void* d_out, int out_size) {
    const int*   recep = (const int*)  d_in[0];
    const float* nf    = (const float*)d_in[1];
    const float* w1    = (const float*)d_in[2];
    const float* b1    = (const float*)d_in[3];
    const float* w2    = (const float*)d_in[4];
    const float* b2    = (const float*)d_in[5];
    const float* fcw   = (const float*)d_in[6];
    const float* fcb   = (const float*)d_in[7];
    float* out = (float*)d_out;

    cudaFuncSetAttribute(conv_kernel, cudaFuncAttributeMaxDynamicSharedMemorySize, SMB_TOTAL);
    prep_kernel<<<(NB*DF*C1 + 255) / 256, 256>>>(w1);
    conv_kernel<<<NCTA, 256, SMB_TOTAL>>>(recep, nf, b1, w2, b2, fcw, fcb, out);
}

// round 17
// speedup vs baseline: 1.2508x; 1.0114x over previous
#include <cuda_runtime.h>
#include <cuda_fp16.h>
#include <cstdint>

#define BSZ   128
#define NNODE 4000
#define DF    128
#define NB    10
#define SEQ   400
#define C1    32
#define C2    32
#define MTILE 128
#define MTOT  (BSZ*SEQ)          // 51200
#define NCTA  (MTOT/MTILE)       // 400
#define NSTAGE 20                // NB * 2 half-K stages

// ---- shared memory byte layout (dynamic) ----------------------------------
#define SMB_IDX   0                         // 1280 u16 recep values = 2560 B
#define SMB_A     2560                      // 2 x 32 KB fp32 half-K stages
#define A_STAGE   (MTILE*64*4)              // 32768
#define SMB_B     (SMB_A + 2*A_STAGE)       // 68096
#define B_STAGE   4096                      // dense 32 pair-rows x 128 B, block-rotated
#define SMB_TOTAL (SMB_B + 2*B_STAGE)       // 76288 -> 3 CTAs/SM

__device__ uint32_t g_w1h[NB*64*32];  // f16 pairs: [k][h][p][rot(blk)*4+nt]
__device__ float    g_partial[MTOT];
__device__ int      g_cnt[BSZ];       // zero-init; self-resetting per call

__device__ __forceinline__ uint32_t smem_u32(const void* p) {
    uint32_t a;
    asm("{ .reg .u64 t; cvta.to.shared.u64 t, %1; cvt.u32.u64 %0, t; }" : "=r"(a) : "l"(p));
    return a;
}
__device__ __forceinline__ void cp16(uint32_t dst, const void* src) {
    asm volatile("cp.async.cg.shared.global [%0], [%1], 16;" :: "r"(dst), "l"(src));
}
// A-gather variant: L2 256B prefetch hint (warp covers exactly one 256B row-half)
__device__ __forceinline__ void cp16_l2(uint32_t dst, const void* src) {
    asm volatile("cp.async.cg.shared.global.L2::256B [%0], [%1], 16;" :: "r"(dst), "l"(src));
}
#define CP_COMMIT() asm volatile("cp.async.commit_group;" ::: "memory")
#define CP_WAIT(N)  asm volatile("cp.async.wait_group %0;" :: "n"(N) : "memory")

__device__ __forceinline__ uint32_t packh2(float2 v) {
    uint32_t r;
    asm("cvt.rn.f16x2.f32 %0, %1, %2;" : "=r"(r) : "f"(v.y), "f"(v.x));
    return r;
}
__device__ __forceinline__ void mma16816(float* c, uint32_t a0, uint32_t a1,
                                         uint32_t a2, uint32_t a3,
                                         uint32_t b0, uint32_t b1) {
    asm volatile(
        "mma.sync.aligned.m16n8k16.row.col.f32.f16.f16.f32 "
        "{%0,%1,%2,%3}, {%4,%5,%6,%7}, {%8,%9}, {%0,%1,%2,%3};"
        : "+f"(c[0]), "+f"(c[1]), "+f"(c[2]), "+f"(c[3])
        : "r"(a0), "r"(a1), "r"(a2), "r"(a3), "r"(b0), "r"(b1));
}

// ---------------------------------------------------------------------------
// prep: conv1 weights -> f16 pairs, [k][h][p]{ blockpos = (blk + 2*(p&3))&7 }
// ---------------------------------------------------------------------------
__global__ void prep_kernel(const float* __restrict__ w1) {
    int i = blockIdx.x * blockDim.x + threadIdx.x;     // 40960
    if (i >= NB * DF * C1) return;
    int k   = i >> 12;
    int rem = i & 4095;
    int d   = rem >> 5;
    int c1  = rem & 31;
    float v = w1[c1 * (DF * NB) + d * NB + k];
    int pair = d >> 1;
    int h    = pair >> 5;
    int p    = pair & 31;
    int perm = ((((c1 & 7) + 2 * (p & 3)) & 7) << 2) + (c1 >> 3);
    ((__half*)g_w1h)[((size_t)k * 2048 + h * 1024 + p * 32 + perm) * 2 + (d & 1)] =
        __float2half_rn(v);
}

// ---------------------------------------------------------------------------
// fused: cp.async pipeline (L2::256B-hinted gather) + f16 mma conv1
//        (LDS.128 B-fragments) + relu + conv2 + relu + FC partial
//        + deterministic last-CTA-per-graph reduction
// ---------------------------------------------------------------------------
__global__ __launch_bounds__(256, 3) void conv_kernel(
    const int*   __restrict__ recep,
    const float* __restrict__ nf,
    const float* __restrict__ b1,
    const float* __restrict__ w2,
    const float* __restrict__ b2,
    const float* __restrict__ fcw,
    const float* __restrict__ fcb,
    float*       __restrict__ out)
{
    extern __shared__ char smem[];
    const uint32_t sbase = smem_u32(smem);
    uint16_t* sIdx16 = (uint16_t*)(smem + SMB_IDX);
    const int tid  = threadIdx.x;
    const int wid  = tid >> 5;
    const int lane = tid & 31;
    const int m0   = blockIdx.x * MTILE;
    const int fr   = lane >> 2;      // 0..7
    const int fc   = lane & 3;       // 0..3

    // u16 recep table: 128 rows x 10 neighbors
    for (int i = tid; i < MTILE * NB; i += 256) {
        int row = i / NB;
        int k   = i - row * NB;
        int m   = m0 + row;
        int b   = m / SEQ;
        int s   = m - b * SEQ;
        sIdx16[i] = (uint16_t)recep[b * NNODE + s * NB + k];
    }
    __syncthreads();

    // per-thread gather constants (slot = tid + j*256 pattern)
    const int rbase = tid >> 4;               // row for j=0; rows rbase + 16j
    const int q     = tid & 15;               // float4 index within row-half
    uint32_t rowbase8[8];                     // graph base byte offsets
#pragma unroll
    for (int j = 0; j < 8; j++) {
        int m = m0 + rbase + j * 16;
        rowbase8[j] = (uint32_t)(m / SEQ) * (NNODE * DF * 4);
    }
    const uint32_t adst = sbase + SMB_A + (uint32_t)rbase * 256u +
                          (uint32_t)((q ^ ((rbase & 7) << 1)) * 16);
    const char* nfq = (const char*)nf + q * 16;

    // stage s: k = s>>1, half h = s&1 (64 K-cols), buffer bi = s&1
    auto prefetch = [&](int s) {
        const int k = s >> 1, h = s & 1, bi = s & 1;
        const char* src0 = nfq + h * 256;
        const int io = rbase * NB + k;
        const uint32_t d0 = adst + (uint32_t)(bi * A_STAGE);
#pragma unroll
        for (int j = 0; j < 8; j++) {
            uint32_t off = (uint32_t)sIdx16[io + j * 160] * 512u + rowbase8[j];
            cp16_l2(d0 + (uint32_t)(j * 4096), src0 + off);
        }
        // B: dense 4 KB, permutation pre-baked in table -> straight copy
        cp16(sbase + SMB_B + (uint32_t)(bi * B_STAGE) + (uint32_t)(tid * 16),
             (const char*)g_w1h + (size_t)k * 8192 + h * 4096 + tid * 16);
        CP_COMMIT();
    };

    prefetch(0);
    prefetch(1);

    float acc[4][4];
#pragma unroll
    for (int nt = 0; nt < 4; nt++)
#pragma unroll
        for (int j = 0; j < 4; j++) acc[nt][j] = 0.f;

    const int row0  = wid * 16 + fr;
    const int sw    = fr << 1;
    const int oi    = (fc & 1) * 2;
    const int bperm = (((fr + 2 * fc) & 7) << 2);   // rotated block for (fr,fc)

    for (int s = 0; s < NSTAGE; s++) {
        const int bi = s & 1;
        if (s < NSTAGE - 1) CP_WAIT(1); else CP_WAIT(0);
        __syncthreads();

        const float*    aw = (const float*)(smem + SMB_A + bi * A_STAGE);
        const uint32_t* bw = (const uint32_t*)(smem + SMB_B + bi * B_STAGE);
#pragma unroll
        for (int t = 0; t < 4; t++) {
            const int q0 = (4 * t + (fc >> 1)) ^ sw;       // cols 16t+2fc
            const int q1 = (4 * t + 2 + (fc >> 1)) ^ sw;   // cols 16t+8+2fc
            float2 v00 = *(const float2*)(aw + row0 * 64       + q0 * 4 + oi);
            float2 v10 = *(const float2*)(aw + (row0 + 8) * 64 + q0 * 4 + oi);
            float2 v01 = *(const float2*)(aw + row0 * 64       + q1 * 4 + oi);
            float2 v11 = *(const float2*)(aw + (row0 + 8) * 64 + q1 * 4 + oi);
            uint32_t a0 = packh2(v00), a1 = packh2(v10);
            uint32_t a2 = packh2(v01), a3 = packh2(v11);
            // B: pair-rows 8t+fc and 8t+4+fc; one LDS.128 each, nt in components
            const uint32_t* bp = bw + (8 * t + fc) * 32 + bperm;
            uint4 bq0 = *(const uint4*)(bp);
            uint4 bq1 = *(const uint4*)(bp + 128);
            mma16816(acc[0], a0, a1, a2, a3, bq0.x, bq1.x);
            mma16816(acc[1], a0, a1, a2, a3, bq0.y, bq1.y);
            mma16816(acc[2], a0, a1, a2, a3, bq0.z, bq1.z);
            mma16816(acc[3], a0, a1, a2, a3, bq0.w, bq1.w);
        }
        __syncthreads();                            // done reading stage bi
        if (s + 2 < NSTAGE) prefetch(s + 2);        // refill freed buffer
    }

    // y1 = relu(conv1 + b1) -> smem [128][33]; w2 -> stage-1 A region
    float* y1s = (float*)(smem + SMB_A);
    float* w2s = (float*)(smem + SMB_A + A_STAGE);
    const int rb = wid * 16;
#pragma unroll
    for (int nt = 0; nt < 4; nt++) {
        int col = nt * 8 + 2 * fc;
        float bc0 = __ldg(b1 + col), bc1 = __ldg(b1 + col + 1);
        y1s[(rb + fr)     * 33 + col]     = fmaxf(acc[nt][0] + bc0, 0.f);
        y1s[(rb + fr)     * 33 + col + 1] = fmaxf(acc[nt][1] + bc1, 0.f);
        y1s[(rb + fr + 8) * 33 + col]     = fmaxf(acc[nt][2] + bc0, 0.f);
        y1s[(rb + fr + 8) * 33 + col + 1] = fmaxf(acc[nt][3] + bc1, 0.f);
    }
    ((float4*)w2s)[tid] = ((const float4*)w2)[tid & 255];
    __syncthreads();

    // conv2 (fp32) + relu + FC partial: one thread per row
    if (tid < MTILE) {
        int m = m0 + tid;
        int b = m / SEQ;
        int s = m - b * SEQ;
        const float* yr = y1s + tid * 33;
        float p = 0.f;
#pragma unroll
        for (int c2 = 0; c2 < C2; c2++) {
            float v = __ldg(b2 + c2);
            const float* wv = w2s + c2 * 32;
#pragma unroll
            for (int qq = 0; qq < 32; qq += 4) {
                v = fmaf(wv[qq],     yr[qq],     v);
                v = fmaf(wv[qq + 1], yr[qq + 1], v);
                v = fmaf(wv[qq + 2], yr[qq + 2], v);
                v = fmaf(wv[qq + 3], yr[qq + 3], v);
            }
            v = fmaxf(v, 0.f);
            p = fmaf(v, __ldg(fcw + c2 * SEQ + s), p);
        }
        g_partial[m] = p;
        __threadfence();
    }
    __syncthreads();

    // --- deterministic final reduction: last CTA to finish a graph sums it
    int*   sfin = (int*)(smem + SMB_B + B_STAGE);      // reuse B stage-1 region
    float* sred = (float*)(smem + SMB_B);              // reuse B stage-0 region
    if (tid == 0) {
        int bA = m0 / SEQ;
        int bB = (m0 + MTILE - 1) / SEQ;
        sfin[0] = -1; sfin[1] = -1;
#pragma unroll 2
        for (int j = 0; j < 2; j++) {
            int b = bA + j;
            if (b > bB) break;
            int lo = max(b * SEQ, m0);
            int hi = min((b + 1) * SEQ, m0 + MTILE);
            int my = hi - lo;
            int old = atomicAdd(&g_cnt[b], my);
            if (old + my == SEQ) sfin[j] = b;
        }
    }
    __syncthreads();

#pragma unroll 2
    for (int j = 0; j < 2; j++) {
        int b = sfin[j];
        if (b < 0) continue;
        __threadfence();                     // acquire other CTAs' partials
        float s = 0.f;
        for (int i = tid; i < SEQ; i += 256) s += g_partial[b * SEQ + i];
        sred[tid] = s;
        __syncthreads();
        for (int st = 128; st > 0; st >>= 1) {
            if (tid < st) sred[tid] += sred[tid + st];
            __syncthreads();
        }
        if (tid == 0) {
            out[b] = sred[0] + __ldg(fcb);
            g_cnt[b] = 0;                    // reset for graph replay
        }
        __syncthreads();
    }
}

// ---------------------------------------------------------------------------
extern "C" void kernel_launch(void* const* d_in, const int* in_sizes, int n_in,
                              void* d_out, int out_size) {
    const int*   recep = (const int*)  d_in[0];
    const float* nf    = (const float*)d_in[1];
    const float* w1    = (const float*)d_in[2];
    const float* b1    = (const float*)d_in[3];
    const float* w2    = (const float*)d_in[4];
    const float* b2    = (const float*)d_in[5];
    const float* fcw   = (const float*)d_in[6];
    const float* fcb   = (const float*)d_in[7];
    float* out = (float*)d_out;

    cudaFuncSetAttribute(conv_kernel, cudaFuncAttributeMaxDynamicSharedMemorySize, SMB_TOTAL);
    prep_kernel<<<(NB*DF*C1 + 255) / 256, 256>>>(w1);
    conv_kernel<<<NCTA, 256, SMB_TOTAL>>>(recep, nf, b1, w2, b2, fcw, fcb, out);
}